// round 1
// baseline (speedup 1.0000x reference)
#include <cuda_runtime.h>

#define NUM_USERS 30000
#define NN 60000            // total nodes
#define EE 800000           // edges
#define KK 64               // embed dim
// intents = 4, D = 16 (4 float4 chunks per intent)

// -------- device scratch (no allocations allowed) --------
__device__ float d_Z1[(size_t)NN * KK];     // iter-1 SpMM result (full Z of routing iter 1)
__device__ float d_Z2[(size_t)NN * KK];     // iter-2 SpMM result (final Z)
__device__ float d_SC[4 * (size_t)EE];      // softmax scores for iter 2, layout [intent][edge]
__device__ int   d_deg[NN];                 // head degree counts
__device__ float d_rs1[NN];                 // 1/sqrt(deg)
__device__ float d_deg2[4 * NN];            // per-intent weighted degrees (iter 2)
__device__ float d_rs2[4 * NN];             // 1/sqrt(deg2)

__device__ __forceinline__ const float4* ego_row(const float* Gu, const float* Gi, int t) {
    const float* p = (t < NUM_USERS) ? (Gu + (size_t)t * KK)
                                     : (Gi + (size_t)(t - NUM_USERS) * KK);
    return reinterpret_cast<const float4*>(p);
}

__device__ __forceinline__ void red_add_v4(float* addr, float4 v) {
    asm volatile("red.global.add.v4.f32 [%0], {%1,%2,%3,%4};"
                 :: "l"(addr), "f"(v.x), "f"(v.y), "f"(v.z), "f"(v.w)
                 : "memory");
}

// -------- kernels --------

// zero all accumulators (graph replays must be self-contained)
__global__ void k_zero() {
    int i = blockIdx.x * blockDim.x + threadIdx.x;
    if (i < NN * KK) { d_Z1[i] = 0.f; d_Z2[i] = 0.f; }
    if (i < NN)      d_deg[i] = 0;
    if (i < 4 * NN)  d_deg2[i] = 0.f;
}

__global__ void k_count_deg(const int* __restrict__ eh) {
    int e = blockIdx.x * blockDim.x + threadIdx.x;
    if (e < EE) atomicAdd(&d_deg[eh[e]], 1);
}

__global__ void k_rs1() {
    int n = blockIdx.x * blockDim.x + threadIdx.x;
    if (n < NN) d_rs1[n] = rsqrtf((float)d_deg[n]);
}

// Routing iter 1: scores==0.25 for every intent -> collapses to a single
// symmetric-normalized SpMM over the full K=64 channels:
//   Z1[h] += (1/sqrt(deg_h * deg_t)) * ego[t]
// 16 threads per edge, one float4 chunk each (coalesced 256B gather per edge).
__global__ void k_spmm1(const float* __restrict__ Gu, const float* __restrict__ Gi,
                        const int* __restrict__ eh, const int* __restrict__ et) {
    int tid = blockIdx.x * blockDim.x + threadIdx.x;
    if (tid >= EE * 16) return;
    int e = tid >> 4, c = tid & 15;
    int h = eh[e], t = et[e];
    float w = d_rs1[h] * d_rs1[t];
    float4 s = __ldg(&ego_row(Gu, Gi, t)[c]);
    float4 v = make_float4(w * s.x, w * s.y, w * s.z, w * s.w);
    red_add_v4(&d_Z1[(size_t)h * KK + c * 4], v);
}

// Fused: attention logit update + softmax over intents + deg2 accumulation.
//   A2[i,e] = 1 + dot( l2norm(Z1[h] chunk_i), tanh(l2norm(ego[t] chunk_i)) )
//   score[i,e] = softmax_i(A2[:,e]);  deg2[i,h] += score[i,e]
// 16 threads/edge: lane c holds float4 chunk c; intent = c>>2.
// Intra-intent reductions: shfl_xor 1,2.  Cross-intent: shfl_xor 4,8.
__global__ void k_attn(const float* __restrict__ Gu, const float* __restrict__ Gi,
                       const int* __restrict__ eh, const int* __restrict__ et) {
    int tid = blockIdx.x * blockDim.x + threadIdx.x;
    if (tid >= EE * 16) return;
    int e = tid >> 4, c = tid & 15;
    int h = eh[e], t = et[e];

    float4 hv = *reinterpret_cast<const float4*>(&d_Z1[(size_t)h * KK + c * 4]);
    float4 tv = __ldg(&ego_row(Gu, Gi, t)[c]);

    float sh = hv.x*hv.x + hv.y*hv.y + hv.z*hv.z + hv.w*hv.w;
    float st = tv.x*tv.x + tv.y*tv.y + tv.z*tv.z + tv.w*tv.w;
    sh += __shfl_xor_sync(0xffffffffu, sh, 1);
    sh += __shfl_xor_sync(0xffffffffu, sh, 2);
    st += __shfl_xor_sync(0xffffffffu, st, 1);
    st += __shfl_xor_sync(0xffffffffu, st, 2);
    float ih = rsqrtf(fmaxf(sh, 1e-12f));
    float it = rsqrtf(fmaxf(st, 1e-12f));

    float p = hv.x * tanhf(tv.x * it) + hv.y * tanhf(tv.y * it)
            + hv.z * tanhf(tv.z * it) + hv.w * tanhf(tv.w * it);
    p *= ih;
    p += __shfl_xor_sync(0xffffffffu, p, 1);
    p += __shfl_xor_sync(0xffffffffu, p, 2);
    float A = 1.f + p;                       // valid on all 4 lanes of this intent

    // softmax across the 4 intents (lanes c, c^4, c^8, c^12)
    float m = fmaxf(A, __shfl_xor_sync(0xffffffffu, A, 4));
    m = fmaxf(m, __shfl_xor_sync(0xffffffffu, m, 8));
    float ex = __expf(A - m);
    float sum = ex + __shfl_xor_sync(0xffffffffu, ex, 4);
    sum = sum + __shfl_xor_sync(0xffffffffu, sum, 8);
    float score = ex / sum;

    if ((c & 3) == 0) {
        int intent = c >> 2;
        d_SC[(size_t)intent * EE + e] = score;
        atomicAdd(&d_deg2[intent * NN + h], score);
    }
}

__global__ void k_rs2() {
    int i = blockIdx.x * blockDim.x + threadIdx.x;
    if (i < 4 * NN) d_rs2[i] = rsqrtf(d_deg2[i]);
}

// Routing iter 2 SpMM (per-intent weights). Final A-update is dead code -> skipped.
//   Z2[h, chunk of intent i] += score[i,e] * rs2[i,t] * rs2[i,h] * ego[t, chunk]
__global__ void k_spmm2(const float* __restrict__ Gu, const float* __restrict__ Gi,
                        const int* __restrict__ eh, const int* __restrict__ et) {
    int tid = blockIdx.x * blockDim.x + threadIdx.x;
    if (tid >= EE * 16) return;
    int e = tid >> 4, c = tid & 15;
    int intent = c >> 2;
    int h = eh[e], t = et[e];
    float score = __ldg(&d_SC[(size_t)intent * EE + e]);
    float w = score * d_rs2[intent * NN + t] * d_rs2[intent * NN + h];
    float4 s = __ldg(&ego_row(Gu, Gi, t)[c]);
    float4 v = make_float4(w * s.x, w * s.y, w * s.z, w * s.w);
    red_add_v4(&d_Z2[(size_t)h * KK + c * 4], v);
}

// out = mean(ego0, Z2) = 0.5*(ego + Z2); output layout = [N, 64] (users then items)
__global__ void k_out(const float* __restrict__ Gu, const float* __restrict__ Gi,
                      float* __restrict__ out) {
    int i = blockIdx.x * blockDim.x + threadIdx.x;   // float4 index
    if (i >= NN * 16) return;
    int n = i >> 4, c = i & 15;
    float4 a = __ldg(&ego_row(Gu, Gi, n)[c]);
    float4 z = *reinterpret_cast<const float4*>(&d_Z2[(size_t)n * KK + c * 4]);
    float4 r = make_float4(0.5f * (a.x + z.x), 0.5f * (a.y + z.y),
                           0.5f * (a.z + z.z), 0.5f * (a.w + z.w));
    reinterpret_cast<float4*>(out)[i] = r;
}

extern "C" void kernel_launch(void* const* d_in, const int* in_sizes, int n_in,
                              void* d_out, int out_size) {
    const float* Gu = (const float*)d_in[0];
    const float* Gi = (const float*)d_in[1];
    const int*   eh = (const int*)d_in[2];
    const int*   et = (const int*)d_in[3];
    float* out = (float*)d_out;

    const int T = 256;
    k_zero<<<(NN * KK + T - 1) / T, T>>>();
    k_count_deg<<<(EE + T - 1) / T, T>>>(eh);
    k_rs1<<<(NN + T - 1) / T, T>>>();
    k_spmm1<<<(EE * 16) / T, T>>>(Gu, Gi, eh, et);
    k_attn<<<(EE * 16) / T, T>>>(Gu, Gi, eh, et);
    k_rs2<<<(4 * NN + T - 1) / T, T>>>();
    k_spmm2<<<(EE * 16) / T, T>>>(Gu, Gi, eh, et);
    k_out<<<(NN * 16 + T - 1) / T, T>>>(Gu, Gi, out);
}

// round 2
// speedup vs baseline: 1.3287x; 1.3287x over previous
#include <cuda_runtime.h>

#define NUM_USERS 30000
#define NN 60000            // total nodes
#define EE 800000           // edges
#define KK 64               // embed dim (4 intents x 16)

// -------- device scratch --------
__device__ float d_Z1[(size_t)NN * KK];   // raw iter-1 scatter (rs1[t]-weighted only; row scale cancels)
__device__ float d_HN[(size_t)NN * KK];   // per-intent l2-normalized Z1
__device__ float d_TT[(size_t)NN * KK];   // tanh(per-intent l2norm(ego))
__device__ float d_Z2[(size_t)NN * KK];   // raw iter-2 scatter (rs2[h] applied in k_out)
__device__ float d_SC[(size_t)EE * 4];    // softmax scores, EDGE-major [e][intent]
__device__ int   d_deg[NN];
__device__ float d_rs1[NN];
__device__ float d_deg2[NN * 4];          // NODE-major [n][intent]
__device__ float d_rs2[NN * 4];

__device__ __forceinline__ const float4* ego_row(const float* Gu, const float* Gi, int t) {
    const float* p = (t < NUM_USERS) ? (Gu + (size_t)t * KK)
                                     : (Gi + (size_t)(t - NUM_USERS) * KK);
    return reinterpret_cast<const float4*>(p);
}

__device__ __forceinline__ void red_add_v4(float* addr, float4 v) {
    asm volatile("red.global.add.v4.f32 [%0], {%1,%2,%3,%4};"
                 :: "l"(addr), "f"(v.x), "f"(v.y), "f"(v.z), "f"(v.w)
                 : "memory");
}

// -------- kernels --------

__global__ void k_init() {
    int i = blockIdx.x * blockDim.x + threadIdx.x;
    if (i < NN * 16) {
        reinterpret_cast<float4*>(d_Z1)[i] = make_float4(0, 0, 0, 0);
        reinterpret_cast<float4*>(d_Z2)[i] = make_float4(0, 0, 0, 0);
    }
    if (i < NN)     d_deg[i] = 0;
    if (i < NN * 4) d_deg2[i] = 0.f;
}

// head degree count, 4 edges/thread
__global__ void k_deg(const int* __restrict__ eh) {
    int g = blockIdx.x * blockDim.x + threadIdx.x;
    if (g >= EE / 4) return;
    int4 h4 = reinterpret_cast<const int4*>(eh)[g];
    atomicAdd(&d_deg[h4.x], 1);
    atomicAdd(&d_deg[h4.y], 1);
    atomicAdd(&d_deg[h4.z], 1);
    atomicAdd(&d_deg[h4.w], 1);
}

// node pass: rs1 + TT = tanh(per-intent l2norm(ego)). 16 threads/node.
__global__ void k_node1(const float* __restrict__ Gu, const float* __restrict__ Gi) {
    int tid = blockIdx.x * blockDim.x + threadIdx.x;
    if (tid >= NN * 16) return;
    int n = tid >> 4, c = tid & 15;
    float4 v = __ldg(&ego_row(Gu, Gi, n)[c]);
    float ss = v.x * v.x + v.y * v.y + v.z * v.z + v.w * v.w;
    ss += __shfl_xor_sync(0xffffffffu, ss, 1);
    ss += __shfl_xor_sync(0xffffffffu, ss, 2);
    float it = rsqrtf(fmaxf(ss, 1e-12f));
    float4 r = make_float4(tanhf(v.x * it), tanhf(v.y * it),
                           tanhf(v.z * it), tanhf(v.w * it));
    reinterpret_cast<float4*>(d_TT)[tid] = r;
    if (c == 0) d_rs1[n] = rsqrtf((float)d_deg[n]);
}

// iter-1 SpMM: Z1[h] += rs1[t] * ego[t].  4 edges per thread, 16 lanes = channels.
__global__ void k_spmm1(const float* __restrict__ Gu, const float* __restrict__ Gi,
                        const int* __restrict__ eh, const int* __restrict__ et) {
    int tid = blockIdx.x * blockDim.x + threadIdx.x;
    int g = tid >> 4, c = tid & 15;
    if (g >= EE / 4) return;
    int4 h4 = __ldg(&reinterpret_cast<const int4*>(eh)[g]);
    int4 t4 = __ldg(&reinterpret_cast<const int4*>(et)[g]);
    int hs[4] = {h4.x, h4.y, h4.z, h4.w};
    int ts[4] = {t4.x, t4.y, t4.z, t4.w};
    float w[4];
    float4 s[4];
#pragma unroll
    for (int j = 0; j < 4; j++) w[j] = __ldg(&d_rs1[ts[j]]);
#pragma unroll
    for (int j = 0; j < 4; j++) s[j] = __ldg(&ego_row(Gu, Gi, ts[j])[c]);
#pragma unroll
    for (int j = 0; j < 4; j++) {
        float4 v = make_float4(w[j] * s[j].x, w[j] * s[j].y, w[j] * s[j].z, w[j] * s[j].w);
        red_add_v4(&d_Z1[(size_t)hs[j] * KK + c * 4], v);
    }
}

// node pass: HN = per-intent l2norm(Z1)
__global__ void k_hn() {
    int tid = blockIdx.x * blockDim.x + threadIdx.x;
    if (tid >= NN * 16) return;
    float4 v = reinterpret_cast<const float4*>(d_Z1)[tid];
    float ss = v.x * v.x + v.y * v.y + v.z * v.z + v.w * v.w;
    ss += __shfl_xor_sync(0xffffffffu, ss, 1);
    ss += __shfl_xor_sync(0xffffffffu, ss, 2);
    float ih = rsqrtf(fmaxf(ss, 1e-12f));
    reinterpret_cast<float4*>(d_HN)[tid] =
        make_float4(v.x * ih, v.y * ih, v.z * ih, v.w * ih);
}

// fused attention + softmax + deg2.  2 edges per thread.
__global__ void k_attn(const int* __restrict__ eh, const int* __restrict__ et) {
    int tid = blockIdx.x * blockDim.x + threadIdx.x;
    int g = tid >> 4, c = tid & 15;
    if (g >= EE / 2) return;
    int2 h2 = __ldg(&reinterpret_cast<const int2*>(eh)[g]);
    int2 t2 = __ldg(&reinterpret_cast<const int2*>(et)[g]);
    int hs[2] = {h2.x, h2.y};
    int ts[2] = {t2.x, t2.y};
    float4 a[2], b[2];
#pragma unroll
    for (int j = 0; j < 2; j++) {
        a[j] = reinterpret_cast<const float4*>(d_HN)[(size_t)hs[j] * 16 + c];
        b[j] = reinterpret_cast<const float4*>(d_TT)[(size_t)ts[j] * 16 + c];
    }
#pragma unroll
    for (int j = 0; j < 2; j++) {
        float p = a[j].x * b[j].x + a[j].y * b[j].y + a[j].z * b[j].z + a[j].w * b[j].w;
        p += __shfl_xor_sync(0xffffffffu, p, 1);
        p += __shfl_xor_sync(0xffffffffu, p, 2);
        float A = 1.f + p;
        float m = fmaxf(A, __shfl_xor_sync(0xffffffffu, A, 4));
        m = fmaxf(m, __shfl_xor_sync(0xffffffffu, m, 8));
        float ex = __expf(A - m);
        float sum = ex + __shfl_xor_sync(0xffffffffu, ex, 4);
        sum = sum + __shfl_xor_sync(0xffffffffu, sum, 8);
        float score = ex / sum;
        if ((c & 3) == 0) {
            int e = 2 * g + j;
            int intent = c >> 2;
            d_SC[(size_t)e * 4 + intent] = score;
            atomicAdd(&d_deg2[hs[j] * 4 + intent], score);
        }
    }
}

__global__ void k_rs2() {
    int i = blockIdx.x * blockDim.x + threadIdx.x;
    if (i < NN * 4) d_rs2[i] = rsqrtf(d_deg2[i]);
}

// iter-2 SpMM: Z2raw[h] += score * rs2[t] * ego[t].  rs2[h] deferred to k_out.
__global__ void k_spmm2(const float* __restrict__ Gu, const float* __restrict__ Gi,
                        const int* __restrict__ eh, const int* __restrict__ et) {
    int tid = blockIdx.x * blockDim.x + threadIdx.x;
    int g = tid >> 4, c = tid & 15;
    if (g >= EE / 4) return;
    int intent = c >> 2;
    int4 h4 = __ldg(&reinterpret_cast<const int4*>(eh)[g]);
    int4 t4 = __ldg(&reinterpret_cast<const int4*>(et)[g]);
    int hs[4] = {h4.x, h4.y, h4.z, h4.w};
    int ts[4] = {t4.x, t4.y, t4.z, t4.w};
    float w[4];
    float4 s[4];
#pragma unroll
    for (int j = 0; j < 4; j++) {
        int e = 4 * g + j;
        w[j] = __ldg(&d_SC[(size_t)e * 4 + intent]) * __ldg(&d_rs2[ts[j] * 4 + intent]);
    }
#pragma unroll
    for (int j = 0; j < 4; j++) s[j] = __ldg(&ego_row(Gu, Gi, ts[j])[c]);
#pragma unroll
    for (int j = 0; j < 4; j++) {
        float4 v = make_float4(w[j] * s[j].x, w[j] * s[j].y, w[j] * s[j].z, w[j] * s[j].w);
        red_add_v4(&d_Z2[(size_t)hs[j] * KK + c * 4], v);
    }
}

// out = 0.5*(ego + rs2[h,intent]*Z2raw)
__global__ void k_out(const float* __restrict__ Gu, const float* __restrict__ Gi,
                      float* __restrict__ out) {
    int i = blockIdx.x * blockDim.x + threadIdx.x;
    if (i >= NN * 16) return;
    int n = i >> 4, c = i & 15;
    float r2 = d_rs2[n * 4 + (c >> 2)];
    float4 a = __ldg(&ego_row(Gu, Gi, n)[c]);
    float4 z = reinterpret_cast<const float4*>(d_Z2)[i];
    reinterpret_cast<float4*>(out)[i] =
        make_float4(0.5f * (a.x + r2 * z.x), 0.5f * (a.y + r2 * z.y),
                    0.5f * (a.z + r2 * z.z), 0.5f * (a.w + r2 * z.w));
}

extern "C" void kernel_launch(void* const* d_in, const int* in_sizes, int n_in,
                              void* d_out, int out_size) {
    const float* Gu = (const float*)d_in[0];
    const float* Gi = (const float*)d_in[1];
    const int*   eh = (const int*)d_in[2];
    const int*   et = (const int*)d_in[3];
    float* out = (float*)d_out;

    const int T = 256;
    k_init <<<(NN * 16 + T - 1) / T, T>>>();
    k_deg  <<<(EE / 4 + T - 1) / T, T>>>(eh);
    k_node1<<<(NN * 16 + T - 1) / T, T>>>(Gu, Gi);
    k_spmm1<<<(EE / 4 * 16 + T - 1) / T, T>>>(Gu, Gi, eh, et);
    k_hn   <<<(NN * 16 + T - 1) / T, T>>>();
    k_attn <<<(EE / 2 * 16 + T - 1) / T, T>>>(eh, et);
    k_rs2  <<<(NN * 4 + T - 1) / T, T>>>();
    k_spmm2<<<(EE / 4 * 16 + T - 1) / T, T>>>(Gu, Gi, eh, et);
    k_out  <<<(NN * 16 + T - 1) / T, T>>>(Gu, Gi, out);
}

// round 3
// speedup vs baseline: 1.6664x; 1.2542x over previous
#include <cuda_runtime.h>

#define NUM_USERS 30000
#define NN 60000            // total nodes
#define EE 800000           // edges
#define KK 64               // embed dim (4 intents x 16)
#define NB 235              // ceil(NN/256) scan blocks

// -------- device scratch --------
__device__ float d_HN[(size_t)NN * KK];   // per-intent l2-normalized Z1 rows
__device__ float d_TT[(size_t)NN * KK];   // tanh(per-intent l2norm(ego))
__device__ float d_SC[(size_t)EE * 4];    // softmax scores, indexed by SORTED edge pos
__device__ int   d_deg[NN];
__device__ float d_rs1[NN];
__device__ float d_deg2[NN * 4];          // node-major [n][intent]
__device__ float d_rs2[NN * 4];
__device__ int   d_rowptr[NN + 1];
__device__ int   d_cursor[NN];
__device__ int   d_sorted_t[EE];          // tails grouped by head
__device__ int   d_partial[256];          // scan block sums

__device__ __forceinline__ const float4* ego_row(const float* Gu, const float* Gi, int t) {
    const float* p = (t < NUM_USERS) ? (Gu + (size_t)t * KK)
                                     : (Gi + (size_t)(t - NUM_USERS) * KK);
    return reinterpret_cast<const float4*>(p);
}

// block-wide exclusive scan of one int per thread (blockDim=256)
__device__ __forceinline__ int block_exscan(int v, int* sm) {
    int lane = threadIdx.x & 31, w = threadIdx.x >> 5;
    int x = v;
#pragma unroll
    for (int d = 1; d < 32; d <<= 1) {
        int y = __shfl_up_sync(0xffffffffu, x, d);
        if (lane >= d) x += y;
    }
    if (lane == 31) sm[w] = x;
    __syncthreads();
    if (w == 0) {
        int s = (lane < 8) ? sm[lane] : 0;
#pragma unroll
        for (int d = 1; d < 8; d <<= 1) {
            int y = __shfl_up_sync(0xffffffffu, s, d);
            if (lane >= d) s += y;
        }
        if (lane < 8) sm[lane] = s;
    }
    __syncthreads();
    int off = (w > 0) ? sm[w - 1] : 0;
    return off + x - v;
}

// -------- kernels --------

__global__ void k_zero() {
    int i = blockIdx.x * blockDim.x + threadIdx.x;
    if (i < NN) d_deg[i] = 0;
}

__global__ void k_deg(const int* __restrict__ eh) {
    int g = blockIdx.x * blockDim.x + threadIdx.x;
    if (g >= EE / 4) return;
    int4 h4 = reinterpret_cast<const int4*>(eh)[g];
    atomicAdd(&d_deg[h4.x], 1);
    atomicAdd(&d_deg[h4.y], 1);
    atomicAdd(&d_deg[h4.z], 1);
    atomicAdd(&d_deg[h4.w], 1);
}

// scan stage 1: per-block sums of deg
__global__ void k_s1() {
    __shared__ int sm[8];
    int i = blockIdx.x * 256 + threadIdx.x;
    int v = (i < NN) ? d_deg[i] : 0;
    int ex = block_exscan(v, sm);
    if (threadIdx.x == 255) d_partial[blockIdx.x] = ex + v;
}

// scan stage 2: exclusive scan of block sums (single block)
__global__ void k_s2() {
    __shared__ int sm[8];
    int v = (threadIdx.x < NB) ? d_partial[threadIdx.x] : 0;
    int ex = block_exscan(v, sm);
    if (threadIdx.x < NB) d_partial[threadIdx.x] = ex;
}

// scan stage 3: full exclusive scan -> rowptr, cursor
__global__ void k_s3() {
    __shared__ int sm[8];
    int i = blockIdx.x * 256 + threadIdx.x;
    int v = (i < NN) ? d_deg[i] : 0;
    int ex = block_exscan(v, sm) + d_partial[blockIdx.x];
    if (i < NN) { d_rowptr[i] = ex; d_cursor[i] = ex; }
    if (i == NN - 1) d_rowptr[NN] = EE;
}

// scatter tails into head-grouped order
__global__ void k_scatter(const int* __restrict__ eh, const int* __restrict__ et) {
    int g = blockIdx.x * blockDim.x + threadIdx.x;
    if (g >= EE / 4) return;
    int4 h4 = __ldg(&reinterpret_cast<const int4*>(eh)[g]);
    int4 t4 = __ldg(&reinterpret_cast<const int4*>(et)[g]);
    d_sorted_t[atomicAdd(&d_cursor[h4.x], 1)] = t4.x;
    d_sorted_t[atomicAdd(&d_cursor[h4.y], 1)] = t4.y;
    d_sorted_t[atomicAdd(&d_cursor[h4.z], 1)] = t4.z;
    d_sorted_t[atomicAdd(&d_cursor[h4.w], 1)] = t4.w;
}

// node pass: rs1 + TT = tanh(per-intent l2norm(ego))
__global__ void k_node1(const float* __restrict__ Gu, const float* __restrict__ Gi) {
    int tid = blockIdx.x * blockDim.x + threadIdx.x;
    if (tid >= NN * 16) return;
    int n = tid >> 4, c = tid & 15;
    float4 v = __ldg(&ego_row(Gu, Gi, n)[c]);
    float ss = v.x * v.x + v.y * v.y + v.z * v.z + v.w * v.w;
    ss += __shfl_xor_sync(0xffffffffu, ss, 1);
    ss += __shfl_xor_sync(0xffffffffu, ss, 2);
    float it = rsqrtf(fmaxf(ss, 1e-12f));
    reinterpret_cast<float4*>(d_TT)[tid] =
        make_float4(tanhf(v.x * it), tanhf(v.y * it), tanhf(v.z * it), tanhf(v.w * it));
    if (c == 0) d_rs1[n] = rsqrtf((float)d_deg[n]);
}

// warp-per-row SpMM1 fused with per-intent l2norm -> HN.
// lanes: half = lane>>4 processes edges start+half, start+half+2, ...
//        c = lane&15 is the float4 channel chunk.
__global__ void k_row1(const float* __restrict__ Gu, const float* __restrict__ Gi) {
    int wid = (blockIdx.x * blockDim.x + threadIdx.x) >> 5;
    if (wid >= NN) return;
    int lane = threadIdx.x & 31, half = lane >> 4, c = lane & 15;
    int start = d_rowptr[wid], end = d_rowptr[wid + 1];
    float4 acc = make_float4(0, 0, 0, 0);
    for (int j = start + half; j < end; j += 2) {
        int t = __ldg(&d_sorted_t[j]);
        float w = __ldg(&d_rs1[t]);
        float4 s = __ldg(&ego_row(Gu, Gi, t)[c]);
        acc.x += w * s.x; acc.y += w * s.y; acc.z += w * s.z; acc.w += w * s.w;
    }
    // combine halves (all lanes converged here)
    acc.x += __shfl_xor_sync(0xffffffffu, acc.x, 16);
    acc.y += __shfl_xor_sync(0xffffffffu, acc.y, 16);
    acc.z += __shfl_xor_sync(0xffffffffu, acc.z, 16);
    acc.w += __shfl_xor_sync(0xffffffffu, acc.w, 16);
    // per-intent l2norm (4 lanes per intent within each half)
    float ss = acc.x * acc.x + acc.y * acc.y + acc.z * acc.z + acc.w * acc.w;
    ss += __shfl_xor_sync(0xffffffffu, ss, 1);
    ss += __shfl_xor_sync(0xffffffffu, ss, 2);
    float ih = rsqrtf(fmaxf(ss, 1e-12f));
    if (half == 0)
        reinterpret_cast<float4*>(d_HN)[(size_t)wid * 16 + c] =
            make_float4(acc.x * ih, acc.y * ih, acc.z * ih, acc.w * ih);
}

// warp-per-row attention: HN[h] loaded once, iterate tails, write SC at sorted
// position, accumulate deg2 in registers (no atomics).
__global__ void k_attn(void) {
    int wid = (blockIdx.x * blockDim.x + threadIdx.x) >> 5;
    if (wid >= NN) return;
    int lane = threadIdx.x & 31, half = lane >> 4, c = lane & 15;
    unsigned hm = half ? 0xFFFF0000u : 0x0000FFFFu;   // in-loop shfl mask per half
    int start = d_rowptr[wid], end = d_rowptr[wid + 1];
    float4 hv = reinterpret_cast<const float4*>(d_HN)[(size_t)wid * 16 + c];
    float dsum = 0.f;
    for (int j = start + half; j < end; j += 2) {
        int t = __ldg(&d_sorted_t[j]);
        float4 b = __ldg(&reinterpret_cast<const float4*>(d_TT)[(size_t)t * 16 + c]);
        float p = hv.x * b.x + hv.y * b.y + hv.z * b.z + hv.w * b.w;
        p += __shfl_xor_sync(hm, p, 1);
        p += __shfl_xor_sync(hm, p, 2);
        float A = 1.f + p;
        float m = fmaxf(A, __shfl_xor_sync(hm, A, 4));
        m = fmaxf(m, __shfl_xor_sync(hm, m, 8));
        float ex = __expf(A - m);
        float sum = ex + __shfl_xor_sync(hm, ex, 4);
        sum = sum + __shfl_xor_sync(hm, sum, 8);
        float score = ex / sum;
        if ((c & 3) == 0) {
            d_SC[(size_t)j * 4 + (c >> 2)] = score;
            dsum += score;
        }
    }
    dsum += __shfl_xor_sync(0xffffffffu, dsum, 16);
    if (half == 0 && (c & 3) == 0)
        d_deg2[wid * 4 + (c >> 2)] = dsum;
}

__global__ void k_rs2() {
    int i = blockIdx.x * blockDim.x + threadIdx.x;
    if (i < NN * 4) d_rs2[i] = rsqrtf(d_deg2[i]);
}

// warp-per-row SpMM2 fused with rs2[h] scale and final mean -> out.
__global__ void k_row2(const float* __restrict__ Gu, const float* __restrict__ Gi,
                       float* __restrict__ out) {
    int wid = (blockIdx.x * blockDim.x + threadIdx.x) >> 5;
    if (wid >= NN) return;
    int lane = threadIdx.x & 31, half = lane >> 4, c = lane & 15;
    int intent = c >> 2;
    int start = d_rowptr[wid], end = d_rowptr[wid + 1];
    float4 acc = make_float4(0, 0, 0, 0);
    for (int j = start + half; j < end; j += 2) {
        int t = __ldg(&d_sorted_t[j]);
        float w = __ldg(&d_SC[(size_t)j * 4 + intent]) * __ldg(&d_rs2[t * 4 + intent]);
        float4 s = __ldg(&ego_row(Gu, Gi, t)[c]);
        acc.x += w * s.x; acc.y += w * s.y; acc.z += w * s.z; acc.w += w * s.w;
    }
    acc.x += __shfl_xor_sync(0xffffffffu, acc.x, 16);
    acc.y += __shfl_xor_sync(0xffffffffu, acc.y, 16);
    acc.z += __shfl_xor_sync(0xffffffffu, acc.z, 16);
    acc.w += __shfl_xor_sync(0xffffffffu, acc.w, 16);
    if (half == 0) {
        float r2 = d_rs2[wid * 4 + intent];
        float4 a = __ldg(&ego_row(Gu, Gi, wid)[c]);
        reinterpret_cast<float4*>(out)[(size_t)wid * 16 + c] =
            make_float4(0.5f * (a.x + r2 * acc.x), 0.5f * (a.y + r2 * acc.y),
                        0.5f * (a.z + r2 * acc.z), 0.5f * (a.w + r2 * acc.w));
    }
}

extern "C" void kernel_launch(void* const* d_in, const int* in_sizes, int n_in,
                              void* d_out, int out_size) {
    const float* Gu = (const float*)d_in[0];
    const float* Gi = (const float*)d_in[1];
    const int*   eh = (const int*)d_in[2];
    const int*   et = (const int*)d_in[3];
    float* out = (float*)d_out;

    const int T = 256;
    const int ROWG = (NN * 32 + T - 1) / T;   // warp-per-row grids
    k_zero   <<<(NN + T - 1) / T, T>>>();
    k_deg    <<<(EE / 4 + T - 1) / T, T>>>(eh);
    k_s1     <<<NB, 256>>>();
    k_s2     <<<1, 256>>>();
    k_s3     <<<NB, 256>>>();
    k_scatter<<<(EE / 4 + T - 1) / T, T>>>(eh, et);
    k_node1  <<<(NN * 16 + T - 1) / T, T>>>(Gu, Gi);
    k_row1   <<<ROWG, T>>>(Gu, Gi);
    k_attn   <<<ROWG, T>>>();
    k_rs2    <<<(NN * 4 + T - 1) / T, T>>>();
    k_row2   <<<ROWG, T>>>(Gu, Gi, out);
}

// round 4
// speedup vs baseline: 1.8183x; 1.0912x over previous
#include <cuda_runtime.h>

#define NUM_USERS 30000
#define NN 60000            // total nodes
#define EE 800000           // edges
#define KK 64               // embed dim (4 intents x 16)
#define NB 235              // ceil(NN/256) scan blocks

// -------- device scratch --------
__device__ float d_TT[(size_t)NN * KK];   // tanh(per-intent l2norm(ego))
__device__ float d_SC[(size_t)EE * 4];    // softmax scores, indexed by SORTED edge pos
__device__ int   d_deg[NN];
__device__ float d_rs1[NN];
__device__ float d_deg2[NN * 4];          // node-major [n][intent]
__device__ int   d_rowptr[NN + 1];
__device__ int   d_cursor[NN];
__device__ int   d_sorted_t[EE];          // tails grouped by head
__device__ int   d_partial[256];          // scan block sums

__device__ __forceinline__ const float4* ego_row(const float* Gu, const float* Gi, int t) {
    const float* p = (t < NUM_USERS) ? (Gu + (size_t)t * KK)
                                     : (Gi + (size_t)(t - NUM_USERS) * KK);
    return reinterpret_cast<const float4*>(p);
}

// block-wide exclusive scan of one int per thread (blockDim=256)
__device__ __forceinline__ int block_exscan(int v, int* sm) {
    int lane = threadIdx.x & 31, w = threadIdx.x >> 5;
    int x = v;
#pragma unroll
    for (int d = 1; d < 32; d <<= 1) {
        int y = __shfl_up_sync(0xffffffffu, x, d);
        if (lane >= d) x += y;
    }
    if (lane == 31) sm[w] = x;
    __syncthreads();
    if (w == 0) {
        int s = (lane < 8) ? sm[lane] : 0;
#pragma unroll
        for (int d = 1; d < 8; d <<= 1) {
            int y = __shfl_up_sync(0xffffffffu, s, d);
            if (lane >= d) s += y;
        }
        if (lane < 8) sm[lane] = s;
    }
    __syncthreads();
    int off = (w > 0) ? sm[w - 1] : 0;
    return off + x - v;
}

// -------- kernels --------

__global__ void k_deg(const int* __restrict__ eh) {
    int g = blockIdx.x * blockDim.x + threadIdx.x;
    if (g >= EE / 4) return;
    int4 h4 = reinterpret_cast<const int4*>(eh)[g];
    atomicAdd(&d_deg[h4.x], 1);
    atomicAdd(&d_deg[h4.y], 1);
    atomicAdd(&d_deg[h4.z], 1);
    atomicAdd(&d_deg[h4.w], 1);
}

// scan stage 1: per-block sums of deg
__global__ void k_s1() {
    __shared__ int sm[8];
    int i = blockIdx.x * 256 + threadIdx.x;
    int v = (i < NN) ? d_deg[i] : 0;
    int ex = block_exscan(v, sm);
    if (threadIdx.x == 255) d_partial[blockIdx.x] = ex + v;
}

// scan stage 2 (final): warp 0 sums partial[0..blockIdx), everyone adds it.
__global__ void k_scan() {
    __shared__ int sm[8];
    __shared__ int base_sh;
    if (threadIdx.x < 32) {
        int s = 0;
        for (int t = threadIdx.x; t < blockIdx.x; t += 32) s += d_partial[t];
#pragma unroll
        for (int d = 16; d >= 1; d >>= 1) s += __shfl_xor_sync(0xffffffffu, s, d);
        if (threadIdx.x == 0) base_sh = s;
    }
    int i = blockIdx.x * 256 + threadIdx.x;
    int v = (i < NN) ? d_deg[i] : 0;
    int ex = block_exscan(v, sm);           // contains __syncthreads (publishes base_sh)
    ex += base_sh;
    if (i < NN) { d_rowptr[i] = ex; d_cursor[i] = ex; }
    if (i == NN - 1) d_rowptr[NN] = EE;
}

#define SCAT_BLKS ((EE / 4 + 255) / 256)
#define NODE_BLKS ((NN * 16 + 255) / 256)

// fused: blocks [0, SCAT_BLKS) scatter tails; rest do node pass (TT, rs1)
__global__ void k_scatter_node(const int* __restrict__ eh, const int* __restrict__ et,
                               const float* __restrict__ Gu, const float* __restrict__ Gi) {
    if (blockIdx.x < SCAT_BLKS) {
        int g = blockIdx.x * blockDim.x + threadIdx.x;
        if (g >= EE / 4) return;
        int4 h4 = __ldg(&reinterpret_cast<const int4*>(eh)[g]);
        int4 t4 = __ldg(&reinterpret_cast<const int4*>(et)[g]);
        d_sorted_t[atomicAdd(&d_cursor[h4.x], 1)] = t4.x;
        d_sorted_t[atomicAdd(&d_cursor[h4.y], 1)] = t4.y;
        d_sorted_t[atomicAdd(&d_cursor[h4.z], 1)] = t4.z;
        d_sorted_t[atomicAdd(&d_cursor[h4.w], 1)] = t4.w;
    } else {
        int tid = (blockIdx.x - SCAT_BLKS) * blockDim.x + threadIdx.x;
        if (tid >= NN * 16) return;
        int n = tid >> 4, c = tid & 15;
        float4 v = __ldg(&ego_row(Gu, Gi, n)[c]);
        float ss = v.x * v.x + v.y * v.y + v.z * v.z + v.w * v.w;
        ss += __shfl_xor_sync(0xffffffffu, ss, 1);
        ss += __shfl_xor_sync(0xffffffffu, ss, 2);
        float it = rsqrtf(fmaxf(ss, 1e-12f));
        reinterpret_cast<float4*>(d_TT)[tid] =
            make_float4(tanhf(v.x * it), tanhf(v.y * it), tanhf(v.z * it), tanhf(v.w * it));
        if (c == 0) d_rs1[n] = rsqrtf((float)d_deg[n]);
    }
}

// Fused warp-per-row: SpMM1 accumulate -> per-intent l2norm (registers only) ->
// attention dot + softmax + SC store + deg2 row sum. d_HN eliminated.
// lanes: half = lane>>4 walks edges start+half, start+half+2, ...; c = lane&15 = chunk.
__global__ void k_row1attn(const float* __restrict__ Gu, const float* __restrict__ Gi) {
    int wid = (blockIdx.x * blockDim.x + threadIdx.x) >> 5;
    if (wid >= NN) return;
    int lane = threadIdx.x & 31, half = lane >> 4, c = lane & 15;
    unsigned hm = half ? 0xFFFF0000u : 0x0000FFFFu;
    int start = d_rowptr[wid], end = d_rowptr[wid + 1];

    // pass 1: accumulate Z1 row = sum rs1[t] * ego[t]
    float4 acc = make_float4(0, 0, 0, 0);
    for (int j = start + half; j < end; j += 2) {
        int t = __ldg(&d_sorted_t[j]);
        float w = __ldg(&d_rs1[t]);
        float4 s = __ldg(&ego_row(Gu, Gi, t)[c]);
        acc.x += w * s.x; acc.y += w * s.y; acc.z += w * s.z; acc.w += w * s.w;
    }
    acc.x += __shfl_xor_sync(0xffffffffu, acc.x, 16);
    acc.y += __shfl_xor_sync(0xffffffffu, acc.y, 16);
    acc.z += __shfl_xor_sync(0xffffffffu, acc.z, 16);
    acc.w += __shfl_xor_sync(0xffffffffu, acc.w, 16);
    float ss = acc.x * acc.x + acc.y * acc.y + acc.z * acc.z + acc.w * acc.w;
    ss += __shfl_xor_sync(0xffffffffu, ss, 1);
    ss += __shfl_xor_sync(0xffffffffu, ss, 2);
    float ih = rsqrtf(fmaxf(ss, 1e-12f));
    float4 hv = make_float4(acc.x * ih, acc.y * ih, acc.z * ih, acc.w * ih);

    // pass 2: attention + softmax + scores + deg2 (register accumulation)
    float dsum = 0.f;
    for (int j = start + half; j < end; j += 2) {
        int t = __ldg(&d_sorted_t[j]);
        float4 b = __ldg(&reinterpret_cast<const float4*>(d_TT)[(size_t)t * 16 + c]);
        float p = hv.x * b.x + hv.y * b.y + hv.z * b.z + hv.w * b.w;
        p += __shfl_xor_sync(hm, p, 1);
        p += __shfl_xor_sync(hm, p, 2);
        float A = 1.f + p;
        float m = fmaxf(A, __shfl_xor_sync(hm, A, 4));
        m = fmaxf(m, __shfl_xor_sync(hm, m, 8));
        float ex = __expf(A - m);
        float sum = ex + __shfl_xor_sync(hm, ex, 4);
        sum = sum + __shfl_xor_sync(hm, sum, 8);
        float score = ex / sum;
        if ((c & 3) == 0) {
            d_SC[(size_t)j * 4 + (c >> 2)] = score;
            dsum += score;
        }
    }
    dsum += __shfl_xor_sync(0xffffffffu, dsum, 16);
    if (half == 0 && (c & 3) == 0)
        d_deg2[wid * 4 + (c >> 2)] = dsum;
}

// warp-per-row SpMM2 fused with rs2 (inline rsqrt) and final mean -> out.
__global__ void k_row2(const float* __restrict__ Gu, const float* __restrict__ Gi,
                       float* __restrict__ out) {
    int wid = (blockIdx.x * blockDim.x + threadIdx.x) >> 5;
    if (wid >= NN) return;
    int lane = threadIdx.x & 31, half = lane >> 4, c = lane & 15;
    int intent = c >> 2;
    int start = d_rowptr[wid], end = d_rowptr[wid + 1];
    float4 acc = make_float4(0, 0, 0, 0);
    for (int j = start + half; j < end; j += 2) {
        int t = __ldg(&d_sorted_t[j]);
        float w = __ldg(&d_SC[(size_t)j * 4 + intent]) *
                  rsqrtf(__ldg(&d_deg2[t * 4 + intent]));
        float4 s = __ldg(&ego_row(Gu, Gi, t)[c]);
        acc.x += w * s.x; acc.y += w * s.y; acc.z += w * s.z; acc.w += w * s.w;
    }
    acc.x += __shfl_xor_sync(0xffffffffu, acc.x, 16);
    acc.y += __shfl_xor_sync(0xffffffffu, acc.y, 16);
    acc.z += __shfl_xor_sync(0xffffffffu, acc.z, 16);
    acc.w += __shfl_xor_sync(0xffffffffu, acc.w, 16);
    if (half == 0) {
        float r2 = rsqrtf(d_deg2[wid * 4 + intent]);
        float4 a = __ldg(&ego_row(Gu, Gi, wid)[c]);
        reinterpret_cast<float4*>(out)[(size_t)wid * 16 + c] =
            make_float4(0.5f * (a.x + r2 * acc.x), 0.5f * (a.y + r2 * acc.y),
                        0.5f * (a.z + r2 * acc.z), 0.5f * (a.w + r2 * acc.w));
    }
}

extern "C" void kernel_launch(void* const* d_in, const int* in_sizes, int n_in,
                              void* d_out, int out_size) {
    const float* Gu = (const float*)d_in[0];
    const float* Gi = (const float*)d_in[1];
    const int*   eh = (const int*)d_in[2];
    const int*   et = (const int*)d_in[3];
    float* out = (float*)d_out;

    void* degp = nullptr;
    cudaGetSymbolAddress(&degp, d_deg);
    cudaMemsetAsync(degp, 0, NN * sizeof(int));

    const int T = 256;
    const int ROWG = (NN * 32 + T - 1) / T;   // warp-per-row grids
    k_deg         <<<(EE / 4 + T - 1) / T, T>>>(eh);
    k_s1          <<<NB, 256>>>();
    k_scan        <<<NB, 256>>>();
    k_scatter_node<<<SCAT_BLKS + NODE_BLKS, T>>>(eh, et, Gu, Gi);
    k_row1attn    <<<ROWG, T>>>(Gu, Gi);
    k_row2        <<<ROWG, T>>>(Gu, Gi, out);
}

// round 5
// speedup vs baseline: 1.8259x; 1.0042x over previous
#include <cuda_runtime.h>
#include <cuda_fp16.h>

#define NUM_USERS 30000
#define NN 60000            // total nodes
#define EE 800000           // edges
#define KK 64               // embed dim (4 intents x 16)
#define NB 235              // ceil(NN/256) scan blocks

// -------- device scratch --------
__device__ __half d_TT16[(size_t)NN * KK];   // fp16 tanh(per-intent l2norm(ego))
__device__ __half d_EGO16[(size_t)NN * KK];  // fp16 rs1[n]*ego[n]  (attention path only)
__device__ float  d_SC[(size_t)EE * 4];      // softmax scores at SORTED edge pos
__device__ int    d_deg[NN];
__device__ float  d_deg2[NN * 4];            // node-major [n][intent]
__device__ int    d_rowptr[NN + 1];
__device__ int    d_cursor[NN];
__device__ int    d_sorted_t[EE];            // tails grouped by head
__device__ int    d_partial[256];            // scan block sums

__device__ __forceinline__ const float4* ego_row(const float* Gu, const float* Gi, int t) {
    const float* p = (t < NUM_USERS) ? (Gu + (size_t)t * KK)
                                     : (Gi + (size_t)(t - NUM_USERS) * KK);
    return reinterpret_cast<const float4*>(p);
}

__device__ __forceinline__ float4 h4_to_f4(uint2 p) {
    float2 a = __half22float2(*reinterpret_cast<const __half2*>(&p.x));
    float2 b = __half22float2(*reinterpret_cast<const __half2*>(&p.y));
    return make_float4(a.x, a.y, b.x, b.y);
}

// block-wide exclusive scan of one int per thread (blockDim=256)
__device__ __forceinline__ int block_exscan(int v, int* sm) {
    int lane = threadIdx.x & 31, w = threadIdx.x >> 5;
    int x = v;
#pragma unroll
    for (int d = 1; d < 32; d <<= 1) {
        int y = __shfl_up_sync(0xffffffffu, x, d);
        if (lane >= d) x += y;
    }
    if (lane == 31) sm[w] = x;
    __syncthreads();
    if (w == 0) {
        int s = (lane < 8) ? sm[lane] : 0;
#pragma unroll
        for (int d = 1; d < 8; d <<= 1) {
            int y = __shfl_up_sync(0xffffffffu, s, d);
            if (lane >= d) s += y;
        }
        if (lane < 8) sm[lane] = s;
    }
    __syncthreads();
    int off = (w > 0) ? sm[w - 1] : 0;
    return off + x - v;
}

// -------- kernels --------

__global__ void k_deg(const int* __restrict__ eh) {
    int g = blockIdx.x * blockDim.x + threadIdx.x;
    if (g >= EE / 4) return;
    int4 h4 = reinterpret_cast<const int4*>(eh)[g];
    atomicAdd(&d_deg[h4.x], 1);
    atomicAdd(&d_deg[h4.y], 1);
    atomicAdd(&d_deg[h4.z], 1);
    atomicAdd(&d_deg[h4.w], 1);
}

__global__ void k_s1() {
    __shared__ int sm[8];
    int i = blockIdx.x * 256 + threadIdx.x;
    int v = (i < NN) ? d_deg[i] : 0;
    int ex = block_exscan(v, sm);
    if (threadIdx.x == 255) d_partial[blockIdx.x] = ex + v;
}

__global__ void k_scan() {
    __shared__ int sm[8];
    __shared__ int base_sh;
    if (threadIdx.x < 32) {
        int s = 0;
        for (int t = threadIdx.x; t < blockIdx.x; t += 32) s += d_partial[t];
#pragma unroll
        for (int d = 16; d >= 1; d >>= 1) s += __shfl_xor_sync(0xffffffffu, s, d);
        if (threadIdx.x == 0) base_sh = s;
    }
    int i = blockIdx.x * 256 + threadIdx.x;
    int v = (i < NN) ? d_deg[i] : 0;
    int ex = block_exscan(v, sm);           // has __syncthreads (publishes base_sh)
    ex += base_sh;
    if (i < NN) { d_rowptr[i] = ex; d_cursor[i] = ex; }
    if (i == NN - 1) d_rowptr[NN] = EE;
}

#define SCAT_BLKS ((EE / 4 + 255) / 256)
#define NODE_BLKS ((NN * 16 + 255) / 256)

// fused: blocks [0, SCAT_BLKS) scatter tails; rest compute TT16 + EGO16
__global__ void k_scatter_node(const int* __restrict__ eh, const int* __restrict__ et,
                               const float* __restrict__ Gu, const float* __restrict__ Gi) {
    if (blockIdx.x < SCAT_BLKS) {
        int g = blockIdx.x * blockDim.x + threadIdx.x;
        if (g >= EE / 4) return;
        int4 h4 = __ldg(&reinterpret_cast<const int4*>(eh)[g]);
        int4 t4 = __ldg(&reinterpret_cast<const int4*>(et)[g]);
        d_sorted_t[atomicAdd(&d_cursor[h4.x], 1)] = t4.x;
        d_sorted_t[atomicAdd(&d_cursor[h4.y], 1)] = t4.y;
        d_sorted_t[atomicAdd(&d_cursor[h4.z], 1)] = t4.z;
        d_sorted_t[atomicAdd(&d_cursor[h4.w], 1)] = t4.w;
    } else {
        int tid = (blockIdx.x - SCAT_BLKS) * blockDim.x + threadIdx.x;
        if (tid >= NN * 16) return;
        int n = tid >> 4, c = tid & 15;
        float4 v = __ldg(&ego_row(Gu, Gi, n)[c]);
        float ss = v.x * v.x + v.y * v.y + v.z * v.z + v.w * v.w;
        ss += __shfl_xor_sync(0xffffffffu, ss, 1);
        ss += __shfl_xor_sync(0xffffffffu, ss, 2);
        float it = rsqrtf(fmaxf(ss, 1e-12f));
        __half2 t0 = __floats2half2_rn(tanhf(v.x * it), tanhf(v.y * it));
        __half2 t1 = __floats2half2_rn(tanhf(v.z * it), tanhf(v.w * it));
        uint2 tp; tp.x = *reinterpret_cast<unsigned*>(&t0);
                  tp.y = *reinterpret_cast<unsigned*>(&t1);
        reinterpret_cast<uint2*>(d_TT16)[tid] = tp;
        float w = rsqrtf((float)d_deg[n]);   // rs1 folded into EGO16
        __half2 e0 = __floats2half2_rn(w * v.x, w * v.y);
        __half2 e1 = __floats2half2_rn(w * v.z, w * v.w);
        uint2 ep; ep.x = *reinterpret_cast<unsigned*>(&e0);
                  ep.y = *reinterpret_cast<unsigned*>(&e1);
        reinterpret_cast<uint2*>(d_EGO16)[tid] = ep;
    }
}

// Fused warp-per-row: SpMM1 (fp16 gathers, rs1 pre-folded) -> per-intent l2norm
// in registers -> attention + softmax + SC + deg2. Unroll-2 per half-warp.
__global__ void k_row1attn() {
    int wid = (blockIdx.x * blockDim.x + threadIdx.x) >> 5;
    if (wid >= NN) return;
    int lane = threadIdx.x & 31, half = lane >> 4, c = lane & 15;
    unsigned hm = half ? 0xFFFF0000u : 0x0000FFFFu;
    int start = d_rowptr[wid], end = d_rowptr[wid + 1];
    const uint2* EG = reinterpret_cast<const uint2*>(d_EGO16);
    const uint2* TT = reinterpret_cast<const uint2*>(d_TT16);

    // pass 1: Z1 row accumulate
    float4 acc = make_float4(0, 0, 0, 0);
    int j = start + half;
    for (; j + 2 < end; j += 4) {
        int t0 = __ldg(&d_sorted_t[j]);
        int t1 = __ldg(&d_sorted_t[j + 2]);
        float4 s0 = h4_to_f4(__ldg(&EG[(size_t)t0 * 16 + c]));
        float4 s1 = h4_to_f4(__ldg(&EG[(size_t)t1 * 16 + c]));
        acc.x += s0.x + s1.x; acc.y += s0.y + s1.y;
        acc.z += s0.z + s1.z; acc.w += s0.w + s1.w;
    }
    if (j < end) {
        int t = __ldg(&d_sorted_t[j]);
        float4 s = h4_to_f4(__ldg(&EG[(size_t)t * 16 + c]));
        acc.x += s.x; acc.y += s.y; acc.z += s.z; acc.w += s.w;
    }
    acc.x += __shfl_xor_sync(0xffffffffu, acc.x, 16);
    acc.y += __shfl_xor_sync(0xffffffffu, acc.y, 16);
    acc.z += __shfl_xor_sync(0xffffffffu, acc.z, 16);
    acc.w += __shfl_xor_sync(0xffffffffu, acc.w, 16);
    float ss = acc.x * acc.x + acc.y * acc.y + acc.z * acc.z + acc.w * acc.w;
    ss += __shfl_xor_sync(0xffffffffu, ss, 1);
    ss += __shfl_xor_sync(0xffffffffu, ss, 2);
    float ih = rsqrtf(fmaxf(ss, 1e-12f));
    float4 hv = make_float4(acc.x * ih, acc.y * ih, acc.z * ih, acc.w * ih);

    // pass 2: attention + softmax + scores + deg2
    float dsum = 0.f;
    j = start + half;
    for (; j + 2 < end; j += 4) {
        int t0 = __ldg(&d_sorted_t[j]);
        int t1 = __ldg(&d_sorted_t[j + 2]);
        float4 b0 = h4_to_f4(__ldg(&TT[(size_t)t0 * 16 + c]));
        float4 b1 = h4_to_f4(__ldg(&TT[(size_t)t1 * 16 + c]));
#pragma unroll
        for (int u = 0; u < 2; u++) {
            float4 b = u ? b1 : b0;
            float p = hv.x * b.x + hv.y * b.y + hv.z * b.z + hv.w * b.w;
            p += __shfl_xor_sync(hm, p, 1);
            p += __shfl_xor_sync(hm, p, 2);
            float A = 1.f + p;
            float m = fmaxf(A, __shfl_xor_sync(hm, A, 4));
            m = fmaxf(m, __shfl_xor_sync(hm, m, 8));
            float ex = __expf(A - m);
            float sum = ex + __shfl_xor_sync(hm, ex, 4);
            sum = sum + __shfl_xor_sync(hm, sum, 8);
            float score = ex / sum;
            if ((c & 3) == 0) {
                d_SC[(size_t)(j + 2 * u) * 4 + (c >> 2)] = score;
                dsum += score;
            }
        }
    }
    if (j < end) {
        int t = __ldg(&d_sorted_t[j]);
        float4 b = h4_to_f4(__ldg(&TT[(size_t)t * 16 + c]));
        float p = hv.x * b.x + hv.y * b.y + hv.z * b.z + hv.w * b.w;
        p += __shfl_xor_sync(hm, p, 1);
        p += __shfl_xor_sync(hm, p, 2);
        float A = 1.f + p;
        float m = fmaxf(A, __shfl_xor_sync(hm, A, 4));
        m = fmaxf(m, __shfl_xor_sync(hm, m, 8));
        float ex = __expf(A - m);
        float sum = ex + __shfl_xor_sync(hm, ex, 4);
        sum = sum + __shfl_xor_sync(hm, sum, 8);
        float score = ex / sum;
        if ((c & 3) == 0) {
            d_SC[(size_t)j * 4 + (c >> 2)] = score;
            dsum += score;
        }
    }
    dsum += __shfl_xor_sync(0xffffffffu, dsum, 16);
    if (half == 0 && (c & 3) == 0)
        d_deg2[wid * 4 + (c >> 2)] = dsum;
}

// warp-per-row SpMM2 fused with rs2 (inline rsqrt) and final mean -> out. Unroll-2.
__global__ void k_row2(const float* __restrict__ Gu, const float* __restrict__ Gi,
                       float* __restrict__ out) {
    int wid = (blockIdx.x * blockDim.x + threadIdx.x) >> 5;
    if (wid >= NN) return;
    int lane = threadIdx.x & 31, half = lane >> 4, c = lane & 15;
    int intent = c >> 2;
    int start = d_rowptr[wid], end = d_rowptr[wid + 1];
    float4 acc = make_float4(0, 0, 0, 0);
    int j = start + half;
    for (; j + 2 < end; j += 4) {
        int t0 = __ldg(&d_sorted_t[j]);
        int t1 = __ldg(&d_sorted_t[j + 2]);
        float w0 = __ldg(&d_SC[(size_t)j * 4 + intent]) *
                   rsqrtf(__ldg(&d_deg2[t0 * 4 + intent]));
        float w1 = __ldg(&d_SC[(size_t)(j + 2) * 4 + intent]) *
                   rsqrtf(__ldg(&d_deg2[t1 * 4 + intent]));
        float4 s0 = __ldg(&ego_row(Gu, Gi, t0)[c]);
        float4 s1 = __ldg(&ego_row(Gu, Gi, t1)[c]);
        acc.x += w0 * s0.x + w1 * s1.x;
        acc.y += w0 * s0.y + w1 * s1.y;
        acc.z += w0 * s0.z + w1 * s1.z;
        acc.w += w0 * s0.w + w1 * s1.w;
    }
    if (j < end) {
        int t = __ldg(&d_sorted_t[j]);
        float w = __ldg(&d_SC[(size_t)j * 4 + intent]) *
                  rsqrtf(__ldg(&d_deg2[t * 4 + intent]));
        float4 s = __ldg(&ego_row(Gu, Gi, t)[c]);
        acc.x += w * s.x; acc.y += w * s.y; acc.z += w * s.z; acc.w += w * s.w;
    }
    acc.x += __shfl_xor_sync(0xffffffffu, acc.x, 16);
    acc.y += __shfl_xor_sync(0xffffffffu, acc.y, 16);
    acc.z += __shfl_xor_sync(0xffffffffu, acc.z, 16);
    acc.w += __shfl_xor_sync(0xffffffffu, acc.w, 16);
    if (half == 0) {
        float r2 = rsqrtf(d_deg2[wid * 4 + intent]);
        float4 a = __ldg(&ego_row(Gu, Gi, wid)[c]);
        reinterpret_cast<float4*>(out)[(size_t)wid * 16 + c] =
            make_float4(0.5f * (a.x + r2 * acc.x), 0.5f * (a.y + r2 * acc.y),
                        0.5f * (a.z + r2 * acc.z), 0.5f * (a.w + r2 * acc.w));
    }
}

extern "C" void kernel_launch(void* const* d_in, const int* in_sizes, int n_in,
                              void* d_out, int out_size) {
    const float* Gu = (const float*)d_in[0];
    const float* Gi = (const float*)d_in[1];
    const int*   eh = (const int*)d_in[2];
    const int*   et = (const int*)d_in[3];
    float* out = (float*)d_out;

    void* degp = nullptr;
    cudaGetSymbolAddress(&degp, d_deg);
    cudaMemsetAsync(degp, 0, NN * sizeof(int));

    const int T = 256;
    const int ROWG = (NN * 32 + T - 1) / T;   // warp-per-row grids
    k_deg         <<<(EE / 4 + T - 1) / T, T>>>(eh);
    k_s1          <<<NB, 256>>>();
    k_scan        <<<NB, 256>>>();
    k_scatter_node<<<SCAT_BLKS + NODE_BLKS, T>>>(eh, et, Gu, Gi);
    k_row1attn    <<<ROWG, T>>>();
    k_row2        <<<ROWG, T>>>(Gu, Gi, out);
}